// round 10
// baseline (speedup 1.0000x reference)
#include <cuda_runtime.h>
#include <cuda_bf16.h>

#define NN 50000
#define KK 17
#define DIN 128
#define DOUT 64

typedef unsigned long long u64;

// Scratch for projected features xp = x @ W : [N, 64] fp32 = 12.8 MB (fits in L2)
__device__ float g_xp[(size_t)NN * DOUT];

// ---------------------------------------------------------------------------
// packed f32x2 fma (SASS FFMA2): d.lo += a.lo*b.lo; d.hi += a.hi*b.hi
// ---------------------------------------------------------------------------
__device__ __forceinline__ void fma2(u64& d, u64 a, u64 b) {
    asm("fma.rn.f32x2 %0, %1, %2, %0;" : "+l"(d) : "l"(a), "l"(b));
}
__device__ __forceinline__ float pairsum(u64 a) {
    const float lo = __uint_as_float((unsigned)(a & 0xffffffffull));
    const float hi = __uint_as_float((unsigned)(a >> 32));
    return lo + hi;
}

// ---------------------------------------------------------------------------
// Kernel 1: xp = x @ W via packed FFMA2.
// Tile: 128 rows x 64 cols (all N), K chunked by 32.
// Accumulator acc[i][j] = {even-k partial, odd-k partial} packed in u64.
//   x pair  {x[r][2p], x[r][2p+1]}   : contiguous u64 in xs  [128][17 u64]
//   w pair  {w[2p][c], w[2p+1][c]}   : contiguous u64 in wp  [64][65 u64]
// Thread map: r0 = tid&15 (rows r0+16i, i<8), c0 = (tid>>4)*4 (4 cols).
//   -> w reads: all lanes in each half-warp share the address (broadcast).
//   -> x reads: 16 distinct rows, odd u64 stride -> conflict-free.
// smem = 17408 + 33280 = 50688 B (dynamic).
// ---------------------------------------------------------------------------
#define XSTRIDE 17   // u64 per xs row (16 pairs + 1 pad)
#define WSTRIDE 65   // u64 per wp row (64 pairs + 1 pad)
#define GEMM_SMEM (128 * XSTRIDE * 8 + 64 * WSTRIDE * 8)

__global__ void __launch_bounds__(256, 2) gemm_kernel(
    const float* __restrict__ x, const float* __restrict__ wm)
{
    extern __shared__ char smem[];
    float* xsf = (float*)smem;                       // [128][34 floats]
    u64*   xsu = (u64*)smem;                         // [128][17 u64]
    float* wpf = (float*)(smem + 128 * XSTRIDE * 8); // [64][130 floats]
    u64*   wpu = (u64*)(smem + 128 * XSTRIDE * 8);   // [64][65 u64]

    const int tid  = threadIdx.x;
    const int row0 = blockIdx.x * 128;
    const int r0   = tid & 15;
    const int c0   = (tid >> 4) * 4;

    // --- stage wp once: wpf[c][k] = wm[k][c]  (pair p=k/2 is u64 [c][p]) ---
#pragma unroll
    for (int i = 0; i < 8; i++) {
        const int idx = tid + 256 * i;     // 0..2047 float4s
        const int k   = idx >> 4;          // 0..127
        const int c   = (idx & 15) * 4;    // 0..60
        const float4 v = *(const float4*)(wm + (size_t)k * DOUT + c);
        wpf[(c + 0) * (2 * WSTRIDE) + k] = v.x;
        wpf[(c + 1) * (2 * WSTRIDE) + k] = v.y;
        wpf[(c + 2) * (2 * WSTRIDE) + k] = v.z;
        wpf[(c + 3) * (2 * WSTRIDE) + k] = v.w;
    }

    u64 acc[8][4];
#pragma unroll
    for (int i = 0; i < 8; i++)
#pragma unroll
        for (int j = 0; j < 4; j++) acc[i][j] = 0ull;

    for (int k0 = 0; k0 < DIN; k0 += 32) {
        if (k0 > 0) __syncthreads();   // previous xs chunk fully consumed
        // --- stage xs chunk: 128 rows x 32 floats ---
#pragma unroll
        for (int i = 0; i < 4; i++) {
            const int f4 = tid + 256 * i;  // 0..1023 float4s
            const int r  = f4 >> 3;        // 0..127
            const int cc = (f4 & 7) * 4;   // 0..28
            int gr = row0 + r;
            if (gr > NN - 1) gr = NN - 1;
            const float4 v = *(const float4*)(x + (size_t)gr * DIN + k0 + cc);
            *(float2*)&xsf[r * (2 * XSTRIDE) + cc]     = make_float2(v.x, v.y);
            *(float2*)&xsf[r * (2 * XSTRIDE) + cc + 2] = make_float2(v.z, v.w);
        }
        __syncthreads();

        const int p0 = k0 >> 1;   // pair offset into wp rows
#pragma unroll
        for (int p = 0; p < 16; p++) {
            u64 wv[4], xv[8];
#pragma unroll
            for (int j = 0; j < 4; j++)
                wv[j] = wpu[(c0 + j) * WSTRIDE + p0 + p];
#pragma unroll
            for (int i = 0; i < 8; i++)
                xv[i] = xsu[(r0 + 16 * i) * XSTRIDE + p];
#pragma unroll
            for (int i = 0; i < 8; i++)
#pragma unroll
                for (int j = 0; j < 4; j++) fma2(acc[i][j], xv[i], wv[j]);
        }
    }

#pragma unroll
    for (int i = 0; i < 8; i++) {
        const int gr = row0 + r0 + 16 * i;
        if (gr < NN) {
            float4 v;
            v.x = pairsum(acc[i][0]);
            v.y = pairsum(acc[i][1]);
            v.z = pairsum(acc[i][2]);
            v.w = pairsum(acc[i][3]);
            *(float4*)&g_xp[(size_t)gr * DOUT + c0] = v;
        }
    }
}

// ---------------------------------------------------------------------------
// Kernel 2: weighted per-dim median (R8 + per-node total precompute).
// Keys: value with low-5 mantissa bits replaced by element index (distinct
// keys; <=31-ulp perturbation). Sort via Green's 60-CE 16-sorter + 16-CE
// serial insertion (76 CEs, 2 FMNMX each, bit-exact -> index rides along).
// Sorted weights recovered by indexed smem read; cumsum walk for the
// half-total crossing. Node totals computed once per node in smem.
// ---------------------------------------------------------------------------
#define CE(A, B) do {                      \
    const float ka_ = k##A, kb_ = k##B;    \
    k##A = fminf(ka_, kb_);                \
    k##B = fmaxf(ka_, kb_);                \
} while (0)

__global__ void __launch_bounds__(256) median_kernel(
    const int*   __restrict__ col,
    const float* __restrict__ ew,
    const float* __restrict__ bias,
    float*       __restrict__ out)
{
    __shared__ float swt[4][KK];
    __shared__ int   soff[4][KK];
    __shared__ float stot[4];

    const int tid   = threadIdx.x;
    const int local = tid >> 6;
    const int d     = tid & 63;
    const int node  = blockIdx.x * 4 + local;

    if (d < KK) {
        swt[local][d]  = ew[node * KK + d];
        soff[local][d] = col[node * KK + d] * DOUT;
    }
    __syncthreads();

    if (d == 0) {
        const float* wl = swt[local];
        stot[local] =
            ((wl[0] + wl[1]) + (wl[2] + wl[3])) +
            ((wl[4] + wl[5]) + (wl[6] + wl[7])) +
            ((wl[8] + wl[9]) + (wl[10] + wl[11])) +
            ((wl[12] + wl[13]) + (wl[14] + wl[15])) + wl[16];
    }

    const float* __restrict__ xpd = g_xp + d;

    // load values, embed index into low 5 mantissa bits (one LOP3 each)
#define LOADJ(J) float k##J = __uint_as_float(                                 \
        (__float_as_uint(__ldg(xpd + soff[local][J])) & 0xFFFFFFE0u) |         \
        (unsigned)J);
    LOADJ(0)  LOADJ(1)  LOADJ(2)  LOADJ(3)  LOADJ(4)  LOADJ(5)
    LOADJ(6)  LOADJ(7)  LOADJ(8)  LOADJ(9)  LOADJ(10) LOADJ(11)
    LOADJ(12) LOADJ(13) LOADJ(14) LOADJ(15) LOADJ(16)
#undef LOADJ

    __syncthreads();
    const float total = stot[local];
    const float hf    = 0.5f * total;

    // --- Green's 16-element 60-CE sorting network on wires 0..15 ---
    CE(0,1);  CE(2,3);  CE(4,5);  CE(6,7);
    CE(8,9);  CE(10,11); CE(12,13); CE(14,15);

    CE(0,2);  CE(1,3);  CE(4,6);  CE(5,7);
    CE(8,10); CE(9,11); CE(12,14); CE(13,15);

    CE(0,4);  CE(1,5);  CE(2,6);  CE(3,7);
    CE(8,12); CE(9,13); CE(10,14); CE(11,15);

    CE(0,8);  CE(1,9);  CE(2,10); CE(3,11);
    CE(4,12); CE(5,13); CE(6,14); CE(7,15);

    CE(5,10); CE(6,9);  CE(3,12); CE(13,14);
    CE(7,11); CE(1,2);  CE(4,8);

    CE(1,4);  CE(7,13); CE(2,8);  CE(11,14);

    CE(2,4);  CE(5,6);  CE(9,10); CE(11,13);

    CE(3,8);  CE(7,12);

    CE(6,8);  CE(10,12); CE(3,5); CE(7,9);

    CE(3,4);  CE(5,6);  CE(7,8);  CE(9,10); CE(11,12);

    CE(6,7);  CE(8,9);

    // --- serial insertion of element 16 into the sorted 0..15 ---
    CE(15,16); CE(14,15); CE(13,14); CE(12,13);
    CE(11,12); CE(10,11); CE(9,10);  CE(8,9);
    CE(7,8);   CE(6,7);   CE(5,6);   CE(4,5);
    CE(3,4);   CE(2,3);   CE(1,2);   CE(0,1);

    // --- recover sorted weights by embedded index (indexed LDS) ---
    const float* wl = swt[local];
#define SWJ(J) const float sw##J = wl[__float_as_uint(k##J) & 31u];
    SWJ(0)  SWJ(1)  SWJ(2)  SWJ(3)  SWJ(4)  SWJ(5)  SWJ(6)  SWJ(7)  SWJ(8)
    SWJ(9)  SWJ(10) SWJ(11) SWJ(12) SWJ(13) SWJ(14) SWJ(15) SWJ(16)
#undef SWJ

    // --- cumsum walk: first sorted element with cumulative weight >= hf ---
    float cum = sw0;
    float med = k0;
#define STEP(J) med = (cum < hf) ? k##J : med; cum += sw##J;
    STEP(1)  STEP(2)  STEP(3)  STEP(4)  STEP(5)  STEP(6)  STEP(7)  STEP(8)
    STEP(9)  STEP(10) STEP(11) STEP(12) STEP(13) STEP(14) STEP(15) STEP(16)
#undef STEP

    const float medv = __uint_as_float(__float_as_uint(med) & 0xFFFFFFE0u);

    out[(size_t)node * DOUT + d] = total * medv + __ldg(&bias[d]);
}

// ---------------------------------------------------------------------------
// Inputs: x[N,128] f32, edge_index[2,E] i32, edge_weight[E] f32,
//         weight[128,64] f32, bias[64] f32. Output: [N,64] f32.
// ---------------------------------------------------------------------------
extern "C" void kernel_launch(void* const* d_in, const int* in_sizes, int n_in,
                              void* d_out, int out_size)
{
    const float* x    = (const float*)d_in[0];
    const int*   ei   = (const int*)  d_in[1];
    const float* ew   = (const float*)d_in[2];
    const float* wm   = (const float*)d_in[3];
    const float* bias = (const float*)d_in[4];
    float*       out  = (float*)d_out;

    const int E = in_sizes[1] / 2;
    const int* col = ei + E;

    static bool attr_set = false;
    if (!attr_set) {
        cudaFuncSetAttribute(gemm_kernel,
                             cudaFuncAttributeMaxDynamicSharedMemorySize,
                             GEMM_SMEM);
        attr_set = true;
    }

    gemm_kernel<<<(NN + 127) / 128, 256, GEMM_SMEM>>>(x, wm);
    median_kernel<<<NN / 4, 256>>>(col, ew, bias, out);
}

// round 12
// speedup vs baseline: 1.0797x; 1.0797x over previous
#include <cuda_runtime.h>
#include <cuda_bf16.h>

#define NN 50000
#define KK 17
#define DIN 128
#define DOUT 64

// Scratch for projected features xp = x @ W : [N, 64] fp32 = 12.8 MB (fits in L2)
__device__ float g_xp[(size_t)NN * DOUT];

// ---------------------------------------------------------------------------
// Kernel 1: xp = x @ W (fp32). R4 version — at the scalar-FFMA roof (~21.3us).
// (tcgen05 unavailable: harness PTX targets compute_103, 'a' features gated.)
// ---------------------------------------------------------------------------
__global__ void __launch_bounds__(256) gemm_kernel(
    const float* __restrict__ x, const float* __restrict__ wm)
{
    __shared__ float xs[128][32];
    __shared__ float ws[32][64];

    const int tid  = threadIdx.x;
    const int row0 = blockIdx.x * 128;
    const int c0   = (tid & 15) * 4;
    const int r0   = (tid >> 4) * 8;

    float acc[8][4];
#pragma unroll
    for (int i = 0; i < 8; i++)
#pragma unroll
        for (int j = 0; j < 4; j++) acc[i][j] = 0.f;

    for (int k0 = 0; k0 < DIN; k0 += 32) {
#pragma unroll
        for (int i = 0; i < 4; i++) {
            const int f4 = tid + 256 * i;
            const int r  = f4 >> 3;
            const int cc = (f4 & 7) * 4;
            int gr = row0 + r;
            if (gr > NN - 1) gr = NN - 1;
            const float4 v = *(const float4*)(x + (size_t)gr * DIN + k0 + cc);
            *(float4*)&xs[r][cc] = v;
        }
#pragma unroll
        for (int i = 0; i < 2; i++) {
            const int f4 = tid + 256 * i;
            const int r  = f4 >> 4;
            const int cc = (f4 & 15) * 4;
            const float4 v = *(const float4*)(wm + (size_t)(k0 + r) * DOUT + cc);
            *(float4*)&ws[r][cc] = v;
        }
        __syncthreads();

#pragma unroll
        for (int kk = 0; kk < 32; kk += 2) {
            const float4 w0 = *(const float4*)&ws[kk][c0];
            const float4 w1 = *(const float4*)&ws[kk + 1][c0];
#pragma unroll
            for (int i = 0; i < 8; i++) {
                const float2 xv = *(const float2*)&xs[r0 + i][kk];
                acc[i][0] += xv.x * w0.x;
                acc[i][1] += xv.x * w0.y;
                acc[i][2] += xv.x * w0.z;
                acc[i][3] += xv.x * w0.w;
                acc[i][0] += xv.y * w1.x;
                acc[i][1] += xv.y * w1.y;
                acc[i][2] += xv.y * w1.z;
                acc[i][3] += xv.y * w1.w;
            }
        }
        __syncthreads();
    }

#pragma unroll
    for (int i = 0; i < 8; i++) {
        const int gr = row0 + r0 + i;
        if (gr < NN) {
            float4 v;
            v.x = acc[i][0]; v.y = acc[i][1]; v.z = acc[i][2]; v.w = acc[i][3];
            *(float4*)&g_xp[(size_t)gr * DOUT + c0] = v;
        }
    }
}

// ---------------------------------------------------------------------------
// Kernel 2: weighted per-dim median, TWO nodes per thread, networks
// interleaved for 2-way ILP (fills FMNMX dependency-stall slots).
// Keys: value with low-5 mantissa bits replaced by element index (distinct
// keys; <=31-ulp perturbation). Sort via Green's 60-CE 16-sorter + 16-CE
// serial insertion (76 CEs, 2 FMNMX each, bit-exact -> index rides along).
// Indexed smem weight recovery; cumsum walk for the half-total crossing.
// ---------------------------------------------------------------------------
#define CE2(A, B) do {                         \
    const float a0_ = kA##A, b0_ = kA##B;      \
    const float a1_ = kB##A, b1_ = kB##B;      \
    kA##A = fminf(a0_, b0_);                   \
    kB##A = fminf(a1_, b1_);                   \
    kA##B = fmaxf(a0_, b0_);                   \
    kB##B = fmaxf(a1_, b1_);                   \
} while (0)

__global__ void __launch_bounds__(256) median_kernel(
    const int*   __restrict__ col,
    const float* __restrict__ ew,
    const float* __restrict__ bias,
    float*       __restrict__ out)
{
    __shared__ float swt[8][KK];
    __shared__ int   soff[8][KK];

    const int tid   = threadIdx.x;
    const int local = tid >> 6;            // 0..3 node-pairs per block
    const int d     = tid & 63;
    const int slotA = local * 2;
    const int slotB = slotA + 1;
    const int nodeA = (blockIdx.x * 4 + local) * 2;
    const int nodeB = nodeA + 1;

    // stage weights + neighbor offsets for the block's 8 nodes
    if (d < 2 * KK) {
        const int which = (d >= KK);
        const int j     = which ? d - KK : d;
        const int slot  = slotA + which;
        const int nd    = nodeA + which;
        swt[slot][j]  = ew[nd * KK + j];
        soff[slot][j] = col[nd * KK + j] * DOUT;
    }
    __syncthreads();

    const float* __restrict__ xpd = g_xp + d;

    // load both nodes' values, embed index into low 5 mantissa bits
#define LOADJ(J)                                                               \
    float kA##J = __uint_as_float(                                             \
        (__float_as_uint(__ldg(xpd + soff[slotA][J])) & 0xFFFFFFE0u) |         \
        (unsigned)J);                                                          \
    float kB##J = __uint_as_float(                                             \
        (__float_as_uint(__ldg(xpd + soff[slotB][J])) & 0xFFFFFFE0u) |         \
        (unsigned)J);
    LOADJ(0)  LOADJ(1)  LOADJ(2)  LOADJ(3)  LOADJ(4)  LOADJ(5)
    LOADJ(6)  LOADJ(7)  LOADJ(8)  LOADJ(9)  LOADJ(10) LOADJ(11)
    LOADJ(12) LOADJ(13) LOADJ(14) LOADJ(15) LOADJ(16)
#undef LOADJ

    const float* wlA = swt[slotA];
    const float* wlB = swt[slotB];
    const float totA =
        ((wlA[0] + wlA[1]) + (wlA[2] + wlA[3])) +
        ((wlA[4] + wlA[5]) + (wlA[6] + wlA[7])) +
        ((wlA[8] + wlA[9]) + (wlA[10] + wlA[11])) +
        ((wlA[12] + wlA[13]) + (wlA[14] + wlA[15])) + wlA[16];
    const float totB =
        ((wlB[0] + wlB[1]) + (wlB[2] + wlB[3])) +
        ((wlB[4] + wlB[5]) + (wlB[6] + wlB[7])) +
        ((wlB[8] + wlB[9]) + (wlB[10] + wlB[11])) +
        ((wlB[12] + wlB[13]) + (wlB[14] + wlB[15])) + wlB[16];
    const float hfA = 0.5f * totA;
    const float hfB = 0.5f * totB;

    // --- Green's 16-element 60-CE sorting network on wires 0..15 (x2 ILP) ---
    CE2(0,1);  CE2(2,3);  CE2(4,5);  CE2(6,7);
    CE2(8,9);  CE2(10,11); CE2(12,13); CE2(14,15);

    CE2(0,2);  CE2(1,3);  CE2(4,6);  CE2(5,7);
    CE2(8,10); CE2(9,11); CE2(12,14); CE2(13,15);

    CE2(0,4);  CE2(1,5);  CE2(2,6);  CE2(3,7);
    CE2(8,12); CE2(9,13); CE2(10,14); CE2(11,15);

    CE2(0,8);  CE2(1,9);  CE2(2,10); CE2(3,11);
    CE2(4,12); CE2(5,13); CE2(6,14); CE2(7,15);

    CE2(5,10); CE2(6,9);  CE2(3,12); CE2(13,14);
    CE2(7,11); CE2(1,2);  CE2(4,8);

    CE2(1,4);  CE2(7,13); CE2(2,8);  CE2(11,14);

    CE2(2,4);  CE2(5,6);  CE2(9,10); CE2(11,13);

    CE2(3,8);  CE2(7,12);

    CE2(6,8);  CE2(10,12); CE2(3,5); CE2(7,9);

    CE2(3,4);  CE2(5,6);  CE2(7,8);  CE2(9,10); CE2(11,12);

    CE2(6,7);  CE2(8,9);

    // --- serial insertion of element 16 (the two chains interleave) ---
    CE2(15,16); CE2(14,15); CE2(13,14); CE2(12,13);
    CE2(11,12); CE2(10,11); CE2(9,10);  CE2(8,9);
    CE2(7,8);   CE2(6,7);   CE2(5,6);   CE2(4,5);
    CE2(3,4);   CE2(2,3);   CE2(1,2);   CE2(0,1);

    // --- recover sorted weights by embedded index (indexed LDS) ---
#define SWJ(J)                                                     \
    const float swA##J = wlA[__float_as_uint(kA##J) & 31u];        \
    const float swB##J = wlB[__float_as_uint(kB##J) & 31u];
    SWJ(0)  SWJ(1)  SWJ(2)  SWJ(3)  SWJ(4)  SWJ(5)  SWJ(6)  SWJ(7)  SWJ(8)
    SWJ(9)  SWJ(10) SWJ(11) SWJ(12) SWJ(13) SWJ(14) SWJ(15) SWJ(16)
#undef SWJ

    // --- cumsum walk (interleaved): first element with cumulative >= hf ---
    float cumA = swA0, cumB = swB0;
    float medA = kA0,  medB = kB0;
#define STEP(J)                                    \
    medA = (cumA < hfA) ? kA##J : medA;            \
    medB = (cumB < hfB) ? kB##J : medB;            \
    cumA += swA##J;                                \
    cumB += swB##J;
    STEP(1)  STEP(2)  STEP(3)  STEP(4)  STEP(5)  STEP(6)  STEP(7)  STEP(8)
    STEP(9)  STEP(10) STEP(11) STEP(12) STEP(13) STEP(14) STEP(15) STEP(16)
#undef STEP

    const float medvA = __uint_as_float(__float_as_uint(medA) & 0xFFFFFFE0u);
    const float medvB = __uint_as_float(__float_as_uint(medB) & 0xFFFFFFE0u);

    const float b = __ldg(&bias[d]);
    out[(size_t)nodeA * DOUT + d] = totA * medvA + b;
    out[(size_t)nodeB * DOUT + d] = totB * medvB + b;
}

// ---------------------------------------------------------------------------
// Inputs: x[N,128] f32, edge_index[2,E] i32, edge_weight[E] f32,
//         weight[128,64] f32, bias[64] f32. Output: [N,64] f32.
// ---------------------------------------------------------------------------
extern "C" void kernel_launch(void* const* d_in, const int* in_sizes, int n_in,
                              void* d_out, int out_size)
{
    const float* x    = (const float*)d_in[0];
    const int*   ei   = (const int*)  d_in[1];
    const float* ew   = (const float*)d_in[2];
    const float* wm   = (const float*)d_in[3];
    const float* bias = (const float*)d_in[4];
    float*       out  = (float*)d_out;

    const int E = in_sizes[1] / 2;
    const int* col = ei + E;

    gemm_kernel<<<(NN + 127) / 128, 256>>>(x, wm);
    median_kernel<<<NN / 8, 256>>>(col, ew, bias, out);   // 8 nodes per block
}